// round 8
// baseline (speedup 1.0000x reference)
#include <cuda_runtime.h>
#include <math.h>

// Router: patch (N=32768, C=32, H=8, W=8) f32, keys (16,32) f32, 3 scalars.
// Output: weights_filtered (N, 16) f32.
//
// Persistent full-occupancy grid (148*8 CTAs). Per warp: L2 prefetch of the
// NEXT patch (cross-iteration latency hiding), coalesced float4 streaming
// loads of this patch, 15-shfl recursive-halving channel reduction,
// permuted-key logits (no lane permute / no normalize pass), rank sort.

#define WARPS_PER_BLOCK 8
#define THREADS (WARPS_PER_BLOCK * 32)
#define GRID_BLOCKS (148 * 8)
#define EXPERTS 16
#define CHANNELS 32
#define PATCH_F4 512            // 32*64 floats / 4
#define PATCH_BYTES 8192

__global__ __launch_bounds__(THREADS, 8) void router_kernel(
    const float* __restrict__ patch,
    const float* __restrict__ keys,
    const float* __restrict__ temp_p,
    const float* __restrict__ beta_p,
    const float* __restrict__ thr_p,
    float* __restrict__ out,
    int n_patches)
{
    __shared__ float keys_s[EXPERTS * 33];            // keys permuted to slot order
    __shared__ float scratch[WARPS_PER_BLOCK][32];

    const int tid  = threadIdx.x;
    const int wid  = tid >> 5;
    const int lane = tid & 31;

    // Stage keys permuted: slot s holds channel c(s) = 2*(s&15) + (s>>4),
    // matching the post-exchange lane->channel mapping. Padded rows (33).
    for (int i = tid; i < EXPERTS * CHANNELS; i += THREADS) {
        int e = i >> 5, s = i & 31;
        int c = 2 * (s & 15) + (s >> 4);
        keys_s[e * 33 + s] = keys[e * CHANNELS + c];
    }

    const float inv_temp = 1.0f / (*temp_p);
    const float beta     = (*beta_p) + 1e-8f;
    const float thr      = *thr_p;
    __syncthreads();

    const int warp_global = blockIdx.x * WARPS_PER_BLOCK + wid;
    const int total_warps = gridDim.x * WARPS_PER_BLOCK;
    const int m = lane & 15;

    for (int patch_id = warp_global; patch_id < n_patches; patch_id += total_warps) {

        // ---- Prefetch NEXT patch into L2 first (fire-and-forget; 64 lines).
        {
            int next_id = patch_id + total_warps;
            if (next_id < n_patches) {
                const char* nb = reinterpret_cast<const char*>(patch)
                               + (size_t)next_id * PATCH_BYTES + lane * 256;
                asm volatile("prefetch.global.L2 [%0];" :: "l"(nb));
                asm volatile("prefetch.global.L2 [%0];" :: "l"(nb + 128));
            }
        }

        // ---- Coalesced streaming load of this patch (prefetched last iter).
        const float4* p4 = reinterpret_cast<const float4*>(patch) + (size_t)patch_id * PATCH_F4;
        float s[16];
#pragma unroll
        for (int i = 0; i < 16; i++) {
            float4 t = __ldcs(&p4[i * 32 + lane]);
            s[i] = (t.x + t.y) + (t.z + t.w);
        }

        // ---- Recursive-halving exchange: 15 shfls. Lane l ends holding the
        // 16-lane sum of value index (l&15) => channel 2*(l&15)+(l>>4).
        float t8[8];
        {
            const bool up = (m & 8);
#pragma unroll
            for (int i = 0; i < 8; i++) {
                float snd = up ? s[i] : s[i + 8];
                float r = __shfl_xor_sync(0xFFFFFFFFu, snd, 8);
                t8[i] = (up ? s[i + 8] : s[i]) + r;
            }
        }
        float t4[4];
        {
            const bool up = (m & 4);
#pragma unroll
            for (int i = 0; i < 4; i++) {
                float snd = up ? t8[i] : t8[i + 4];
                float r = __shfl_xor_sync(0xFFFFFFFFu, snd, 4);
                t4[i] = (up ? t8[i + 4] : t8[i]) + r;
            }
        }
        float t2[2];
        {
            const bool up = (m & 2);
#pragma unroll
            for (int i = 0; i < 2; i++) {
                float snd = up ? t4[i] : t4[i + 2];
                float r = __shfl_xor_sync(0xFFFFFFFFu, snd, 2);
                t2[i] = (up ? t4[i + 2] : t4[i]) + r;
            }
        }
        float chansum;
        {
            const bool up = (m & 1);
            float snd = up ? t2[0] : t2[1];
            float r = __shfl_xor_sync(0xFFFFFFFFu, snd, 1);
            chansum = (up ? t2[1] : t2[0]) + r;
        }

        // chansum = 64 * emb[channel(lane)], scrambled slot order. Keys are
        // staged in the same slot order, so no permute needed.
        scratch[wid][lane] = chansum;

        // Sum of squares across all 32 slots (all channels) — full butterfly.
        float sq = chansum * chansum;
#pragma unroll
        for (int k = 16; k; k >>= 1) sq += __shfl_xor_sync(0xFFFFFFFFu, sq, k);
        // sqrt(sq) = 64*||emb||; reference clamps ||emb|| at 1e-12.
        const float inv_n = 1.0f / fmaxf(sqrtf(sq), 6.4e-11f);
        __syncwarp();

        // ---- Logits: lane e (<16) dot over 32 slots with permuted keys ----
        float logit = 0.0f;
        if (lane < EXPERTS) {
            const float* kr = &keys_s[lane * 33];
#pragma unroll
            for (int c = 0; c < CHANNELS; c++)
                logit = fmaf(scratch[wid][c], kr[c], logit);
        }
        __syncwarp();

        float sl = logit * inv_n * inv_temp + 1e-8f;

        // ---- Softmax over 16 lanes ----
        float mx = sl;
#pragma unroll
        for (int k = 8; k; k >>= 1) mx = fmaxf(mx, __shfl_xor_sync(0xFFFFFFFFu, mx, k));
        float ew = __expf(sl - mx);
        float denom = ew;
#pragma unroll
        for (int k = 8; k; k >>= 1) denom += __shfl_xor_sync(0xFFFFFFFFu, denom, k);
        float w = ew / denom;

        // ---- Moments / entropy ----
        float sw   = w;
        float swsq = w * w;
        float swl  = w * __logf(w + 1e-18f);
#pragma unroll
        for (int k = 8; k; k >>= 1) {
            sw   += __shfl_xor_sync(0xFFFFFFFFu, sw,   k);
            swsq += __shfl_xor_sync(0xFFFFFFFFu, swsq, k);
            swl  += __shfl_xor_sync(0xFFFFFFFFu, swl,  k);
        }

        // ---- Descending sort via rank (stable tie-break by index) ----
        if (lane < EXPERTS) scratch[wid][lane] = w;
        __syncwarp();
        if (lane < EXPERTS) {
            int rank = 0;
#pragma unroll
            for (int j = 0; j < EXPERTS; j++) {
                float wj = scratch[wid][j];
                rank += (wj > w) || (wj == w && j < lane);
            }
            scratch[wid][16 + rank] = w;
        }
        __syncwarp();

        const float s0 = scratch[wid][16 + 0];
        const float s1 = scratch[wid][16 + 1];
        const float s2 = scratch[wid][16 + 2];
        const float s3 = scratch[wid][16 + 3];
        const float s4 = scratch[wid][16 + 4];
        __syncwarp();   // consumed before next iteration overwrites

        // ---- Adaptive threshold ----
        const float mean    = sw * (1.0f / 16.0f);
        const float var     = fmaxf(0.0f, (swsq - sw * sw * (1.0f / 16.0f)) * (1.0f / 15.0f));
        const float stdw    = sqrtf(var);
        const float entropy = -swl;

        const float max_comp = 1.0f - s0;
        const float ent_comp = 1.0f - entropy * 0.360673760222f;  // 1/ln(16)
        const float mean_rest = (s1 + s2 + s3 + s4) * 0.25f;
        float gap = (s0 - mean_rest) / (s0 + 1e-8f);
        gap = fminf(fmaxf(gap, 0.0f), 1.0f);

        float adaptive = thr * (0.5f + 0.4f * max_comp + 0.3f * ent_comp + 0.3f * gap);
        const float min_thr = fmaxf(0.05f, mean - 0.5f * stdw);
        const float max_thr = fminf(0.7f, s0 - 0.1f * stdw);
        adaptive = fminf(fmaxf(adaptive, min_thr), max_thr);
        adaptive = fminf(adaptive, s3 * 0.9f);

        // ---- Soft mask, filter, renormalize ----
        const float mask = 1.0f / (1.0f + __expf(-beta * (w - adaptive)));
        float wf = w * mask;
        float swf = wf;
#pragma unroll
        for (int k = 8; k; k >>= 1) swf += __shfl_xor_sync(0xFFFFFFFFu, swf, k);
        const float o = wf / fmaxf(swf, 1e-8f);

        if (lane < EXPERTS)
            out[(size_t)patch_id * EXPERTS + lane] = o;
    }
}

extern "C" void kernel_launch(void* const* d_in, const int* in_sizes, int n_in,
                              void* d_out, int out_size)
{
    const float* patch  = (const float*)d_in[0];
    const float* keys   = (const float*)d_in[1];
    const float* temp_p = (const float*)d_in[2];
    const float* beta_p = (const float*)d_in[3];
    const float* thr_p  = (const float*)d_in[4];
    float* out = (float*)d_out;

    const int n_patches = in_sizes[0] / (CHANNELS * 64);   // 32768
    int blocks = GRID_BLOCKS;
    int needed = (n_patches + WARPS_PER_BLOCK - 1) / WARPS_PER_BLOCK;
    if (needed < blocks) blocks = needed;

    router_kernel<<<blocks, THREADS>>>(patch, keys, temp_p, beta_p, thr_p, out, n_patches);
}

// round 9
// speedup vs baseline: 1.4565x; 1.4565x over previous
#include <cuda_runtime.h>
#include <math.h>

// Router: patch (N=32768, C=32, H=8, W=8) f32, keys (16,32) f32, 3 scalars.
// Output: weights_filtered (N, 16) f32.
//
// Two patches per warp: patch A occupies lanes 0-15, patch B lanes 16-31 for
// the entire post-logit phase (all reductions use xor masks {8,4,2,1} which
// stay within each half-warp). 32 front-batched LDG.128 per warp (4KB in
// flight), 2x ILP on the shfl reduction chains, fully-coalesced 128B output.

#define WARPS_PER_BLOCK 8
#define THREADS (WARPS_PER_BLOCK * 32)
#define EXPERTS 16
#define CHANNELS 32
#define PATCH_F4 512            // 32*64 floats / 4

__device__ __forceinline__ float reduce_exchange(const float* v, int m)
{
    // 16 values/lane -> lane l holds full 16-lane sum of value index (l&15),
    // i.e. channel 2*(l&15) + (l>>4). 15 shfls.
    float t8[8];
    {
        const bool up = (m & 8);
#pragma unroll
        for (int i = 0; i < 8; i++) {
            float snd = up ? v[i] : v[i + 8];
            float r = __shfl_xor_sync(0xFFFFFFFFu, snd, 8);
            t8[i] = (up ? v[i + 8] : v[i]) + r;
        }
    }
    float t4[4];
    {
        const bool up = (m & 4);
#pragma unroll
        for (int i = 0; i < 4; i++) {
            float snd = up ? t8[i] : t8[i + 4];
            float r = __shfl_xor_sync(0xFFFFFFFFu, snd, 4);
            t4[i] = (up ? t8[i + 4] : t8[i]) + r;
        }
    }
    float t2[2];
    {
        const bool up = (m & 2);
#pragma unroll
        for (int i = 0; i < 2; i++) {
            float snd = up ? t4[i] : t4[i + 2];
            float r = __shfl_xor_sync(0xFFFFFFFFu, snd, 2);
            t2[i] = (up ? t4[i + 2] : t4[i]) + r;
        }
    }
    {
        const bool up = (m & 1);
        float snd = up ? t2[0] : t2[1];
        float r = __shfl_xor_sync(0xFFFFFFFFu, snd, 1);
        return (up ? t2[1] : t2[0]) + r;
    }
}

__global__ __launch_bounds__(THREADS, 4) void router_kernel(
    const float* __restrict__ patch,
    const float* __restrict__ keys,
    const float* __restrict__ temp_p,
    const float* __restrict__ beta_p,
    const float* __restrict__ thr_p,
    float* __restrict__ out,
    int n_patches)
{
    __shared__ float keys_s[EXPERTS * 33];        // keys permuted to slot order
    __shared__ float buf[WARPS_PER_BLOCK][64];    // chansums A|B, weights, sorted

    const int tid  = threadIdx.x;
    const int wid  = tid >> 5;
    const int lane = tid & 31;

    // Stage keys permuted: slot s holds channel c(s) = 2*(s&15) + (s>>4),
    // matching the post-exchange lane->channel mapping. Padded rows (33).
    for (int i = tid; i < EXPERTS * CHANNELS; i += THREADS) {
        int e = i >> 5, sl_ = i & 31;
        int c = 2 * (sl_ & 15) + (sl_ >> 4);
        keys_s[e * 33 + sl_] = keys[e * CHANNELS + c];
    }

    const float inv_temp = 1.0f / (*temp_p);
    const float beta     = (*beta_p) + 1e-8f;
    const float thr      = *thr_p;
    __syncthreads();

    // This warp's patch pair: A = pid, B = pid + 1 (contiguous in memory).
    const int pid = 2 * (blockIdx.x * WARPS_PER_BLOCK + wid);
    if (pid >= n_patches) return;
    const bool has_b = (pid + 1) < n_patches;
    const int m = lane & 15;

    // ---- 32 front-batched coalesced streaming loads (A then B, contiguous).
    const float4* p4 = reinterpret_cast<const float4*>(patch) + (size_t)pid * PATCH_F4;
    const int nb_off = has_b ? (16 * 32) : 0;     // degenerate: B aliases A
    float s[32];
#pragma unroll
    for (int i = 0; i < 16; i++) {
        float4 t = __ldcs(&p4[i * 32 + lane]);
        s[i] = (t.x + t.y) + (t.z + t.w);
    }
#pragma unroll
    for (int i = 0; i < 16; i++) {
        float4 t = __ldcs(&p4[nb_off + i * 32 + lane]);
        s[16 + i] = (t.x + t.y) + (t.z + t.w);
    }

    // ---- Channel reduction for both patches (independent chains -> ILP).
    const float cA = reduce_exchange(s,      m);   // 64*embA[channel(lane)]
    const float cB = reduce_exchange(s + 16, m);   // 64*embB[channel(lane)]

    buf[wid][lane]      = cA;                      // A chansums in [0:32)
    buf[wid][32 + lane] = cB;                      // B chansums in [32:64)

    // ---- Norms: full-warp butterflies over each patch's 32 slots.
    float sqA = cA * cA;
    float sqB = cB * cB;
#pragma unroll
    for (int k = 16; k; k >>= 1) {
        sqA += __shfl_xor_sync(0xFFFFFFFFu, sqA, k);
        sqB += __shfl_xor_sync(0xFFFFFFFFu, sqB, k);
    }
    // sqrt = 64*||emb||; reference clamps ||emb|| at 1e-12.
    const float inv_n = 1.0f / fmaxf(sqrtf((lane & 16) ? sqB : sqA), 6.4e-11f);
    __syncwarp();

    // ---- Logits: lanes 0-15 -> patch A experts, lanes 16-31 -> patch B.
    const float* cbase = &buf[wid][(lane & 16) << 1];   // 0 or 32
    const float* kr    = &keys_s[(lane & 15) * 33];
    float logit = 0.0f;
#pragma unroll
    for (int c = 0; c < CHANNELS; c++)
        logit = fmaf(cbase[c], kr[c], logit);
    __syncwarp();

    const float sl = logit * inv_n * inv_temp + 1e-8f;

    // ---- Softmax (masks 8,4,2,1 stay within each 16-lane half) ----
    float mx = sl;
#pragma unroll
    for (int k = 8; k; k >>= 1) mx = fmaxf(mx, __shfl_xor_sync(0xFFFFFFFFu, mx, k));
    float ew = __expf(sl - mx);
    float denom = ew;
#pragma unroll
    for (int k = 8; k; k >>= 1) denom += __shfl_xor_sync(0xFFFFFFFFu, denom, k);
    const float w = ew / denom;

    // ---- Moments / entropy (per-half) ----
    float sw   = w;
    float swsq = w * w;
    float swl  = w * __logf(w + 1e-18f);
#pragma unroll
    for (int k = 8; k; k >>= 1) {
        sw   += __shfl_xor_sync(0xFFFFFFFFu, sw,   k);
        swsq += __shfl_xor_sync(0xFFFFFFFFu, swsq, k);
        swl  += __shfl_xor_sync(0xFFFFFFFFu, swl,  k);
    }

    // ---- Descending sort via rank, per half (stable tie-break by slot) ----
    buf[wid][lane] = w;            // A weights [0:16), B weights [16:32)
    __syncwarp();
    const int base = lane & 16;
    {
        int rank = 0;
#pragma unroll
        for (int j = 0; j < EXPERTS; j++) {
            float wj = buf[wid][base + j];
            rank += (wj > w) || (wj == w && (base + j) < lane);
        }
        buf[wid][32 + base + rank] = w;   // sorted: A [32:48), B [48:64)
    }
    __syncwarp();

    const float s0 = buf[wid][32 + base + 0];
    const float s1 = buf[wid][32 + base + 1];
    const float s2 = buf[wid][32 + base + 2];
    const float s3 = buf[wid][32 + base + 3];
    const float s4 = buf[wid][32 + base + 4];

    // ---- Adaptive threshold ----
    const float mean    = sw * (1.0f / 16.0f);
    const float var     = fmaxf(0.0f, (swsq - sw * sw * (1.0f / 16.0f)) * (1.0f / 15.0f));
    const float stdw    = sqrtf(var);
    const float entropy = -swl;

    const float max_comp = 1.0f - s0;
    const float ent_comp = 1.0f - entropy * 0.360673760222f;  // 1/ln(16)
    const float mean_rest = (s1 + s2 + s3 + s4) * 0.25f;
    float gap = (s0 - mean_rest) / (s0 + 1e-8f);
    gap = fminf(fmaxf(gap, 0.0f), 1.0f);

    float adaptive = thr * (0.5f + 0.4f * max_comp + 0.3f * ent_comp + 0.3f * gap);
    const float min_thr = fmaxf(0.05f, mean - 0.5f * stdw);
    const float max_thr = fminf(0.7f, s0 - 0.1f * stdw);
    adaptive = fminf(fmaxf(adaptive, min_thr), max_thr);
    adaptive = fminf(adaptive, s3 * 0.9f);

    // ---- Soft mask, filter, renormalize (per half) ----
    const float mask = 1.0f / (1.0f + __expf(-beta * (w - adaptive)));
    float wf = w * mask;
    float swf = wf;
#pragma unroll
    for (int k = 8; k; k >>= 1) swf += __shfl_xor_sync(0xFFFFFFFFu, swf, k);
    const float o = wf / fmaxf(swf, 1e-8f);

    // Full-warp coalesced 128B store: lane writes out[pid*16 + lane].
    if (lane < 16 || has_b)
        out[(size_t)pid * EXPERTS + lane] = o;
}

extern "C" void kernel_launch(void* const* d_in, const int* in_sizes, int n_in,
                              void* d_out, int out_size)
{
    const float* patch  = (const float*)d_in[0];
    const float* keys   = (const float*)d_in[1];
    const float* temp_p = (const float*)d_in[2];
    const float* beta_p = (const float*)d_in[3];
    const float* thr_p  = (const float*)d_in[4];
    float* out = (float*)d_out;

    const int n_patches = in_sizes[0] / (CHANNELS * 64);   // 32768
    const int pairs_per_block = WARPS_PER_BLOCK;           // 2 patches per warp
    const int blocks = (n_patches + 2 * pairs_per_block - 1) / (2 * pairs_per_block);

    router_kernel<<<blocks, THREADS>>>(patch, keys, temp_p, beta_p, thr_p, out, n_patches);
}